// round 14
// baseline (speedup 1.0000x reference)
#include <cuda_runtime.h>
#include <cuda_fp16.h>

#define NN 65536
#define NE 1048576
#define DD 64
#define NL 12
#define NM 2
#define AST 68   // As_T row stride (floats)

// ---- device scratch (static allocation only) ----
__device__ __half g_hA[NM][NN * DD];     // fp16 ping
__device__ __half g_hB[NM][NN * DD];     // fp16 pong
__device__ float g_dinv[NM][NN];
__device__ int   g_deg[NM][NN];
__device__ int   g_rowstart[NM][NN + 1];
__device__ int   g_cursor[NM][NN];
__device__ int2  g_csr[NM][NE];          // {src, bitcast(dinv[src])}
__device__ int   g_bsum[NM * 256];
__device__ int   g_boff[NM * 256];

// ---- f32x2 packed helpers ----
__device__ __forceinline__ unsigned long long d_bcast2(float x) {
    unsigned long long r;
    asm("mov.b64 %0, {%1, %1};" : "=l"(r) : "f"(x));
    return r;
}
__device__ __forceinline__ void d_fma2(unsigned long long& d,
                                       unsigned long long a,
                                       unsigned long long b) {
    asm("fma.rn.f32x2 %0, %1, %2, %3;" : "=l"(d) : "l"(a), "l"(b), "l"(d));
}
__device__ __forceinline__ float2 d_unpack2(unsigned long long v) {
    float2 f;
    asm("mov.b64 {%0, %1}, %2;" : "=f"(f.x), "=f"(f.y) : "l"(v));
    return f;
}

// ---------------- CSR build ----------------
__global__ void k_zero_deg() {
    int i = blockIdx.x * blockDim.x + threadIdx.x;
    ((int*)g_deg)[i] = 0;
}

__global__ void k_count(const int* __restrict__ ei) {
    int gi = blockIdx.x * blockDim.x + threadIdx.x;
    int m = gi >> 20;
    int e = gi & (NE - 1);
    int d = ei[(size_t)m * 2 * NE + NE + e] & (NN - 1);
    atomicAdd(&g_deg[m][d], 1);
}

__global__ void k_blocksum() {
    __shared__ int red[256];
    int m = blockIdx.x >> 8;
    int cb = blockIdx.x & 255;
    int node = cb * 256 + threadIdx.x;
    int d = g_deg[m][node];
    g_dinv[m][node] = rsqrtf((float)d + 1.0f);
    red[threadIdx.x] = d;
    __syncthreads();
    for (int off = 128; off > 0; off >>= 1) {
        if (threadIdx.x < off) red[threadIdx.x] += red[threadIdx.x + off];
        __syncthreads();
    }
    if (threadIdx.x == 0) g_bsum[m * 256 + cb] = red[0];
}

__global__ void k_scanb() {
    __shared__ int s[256];
    int t = threadIdx.x;
    int v = g_bsum[blockIdx.x * 256 + t];
    s[t] = v;
    __syncthreads();
    for (int off = 1; off < 256; off <<= 1) {
        int u = (t >= off) ? s[t - off] : 0;
        __syncthreads();
        s[t] += u;
        __syncthreads();
    }
    g_boff[blockIdx.x * 256 + t] = s[t] - v;
}

__global__ void k_rowstart() {
    __shared__ int s[256];
    int m = blockIdx.x >> 8;
    int cb = blockIdx.x & 255;
    int t = threadIdx.x;
    int node = cb * 256 + t;
    int d = g_deg[m][node];
    s[t] = d;
    __syncthreads();
    for (int off = 1; off < 256; off <<= 1) {
        int u = (t >= off) ? s[t - off] : 0;
        __syncthreads();
        s[t] += u;
        __syncthreads();
    }
    int rs = g_boff[m * 256 + cb] + s[t] - d;
    g_rowstart[m][node] = rs;
    g_cursor[m][node] = rs;
    if (node == NN - 1) g_rowstart[m][NN] = rs + d;
}

__global__ void k_fill(const int* __restrict__ ei) {
    int gi = blockIdx.x * blockDim.x + threadIdx.x;
    int m = gi >> 20;
    int e = gi & (NE - 1);
    int s = ei[(size_t)m * 2 * NE + e] & (NN - 1);
    int d = ei[(size_t)m * 2 * NE + NE + e] & (NN - 1);
    int pos = atomicAdd(&g_cursor[m][d], 1);
    g_csr[m][pos] = make_int2(s, __float_as_int(g_dinv[m][s]));
}

// ---------------- fused layer ----------------
// Phase 1: EDGE-BALANCED gather. Each of 32 groups (8 lanes) processes an equal
// contiguous slice of the tile's CSR edge range; partial sums flushed to smem
// via atomicAdd on node-boundary crossings. Phase 1.5: scale + self-loop.
// Phase 2: f32x2 GEMM.
template<bool IN16, bool OUT16>
__global__ __launch_bounds__(256) void k_layer(
    const void* __restrict__ hin,
    void* __restrict__ hout,
    const float* __restrict__ Wbase,
    const float* __restrict__ bbase,
    int j, int relu)
{
    __shared__ float As[64 * AST];   // TRANSPOSED: As[k][nl]
    __shared__ float Ws[64 * 64];
    __shared__ int   rs_s[65];

    int tid = threadIdx.x;
    int m = blockIdx.x >> 10;
    int tile = blockIdx.x & 1023;
    int base = tile * 64;

    const float* Wj = Wbase + ((size_t)m * NL + j) * DD * DD;
    const float* bj = bbase + ((size_t)m * NL + j) * DD;

    // load W tile + rowstart window + zero As
    {
        const float4* W4 = (const float4*)Wj;
        float4* Ws4 = (float4*)Ws;
#pragma unroll
        for (int k = 0; k < 4; k++) Ws4[tid + k * 256] = W4[tid + k * 256];
    }
    if (tid < 65) rs_s[tid] = g_rowstart[m][base + tid];
    for (int i = tid; i < 64 * AST; i += 256) As[i] = 0.f;
    __syncthreads();

    int t = tid & 7;         // feature lane (8 features: t*8 .. t*8+7)
    int grp = tid >> 3;      // 32 edge-slice groups

    const int2* csr = g_csr[m];
    const uint4*  h16 = (const uint4*)hin + (IN16 ? (size_t)m * NN * 8 : 0);
    const float4* h32 = (const float4*)hin + (IN16 ? 0 : (size_t)m * NN * 16);

    // ---- Phase 1: edge-balanced gather ----
    {
        int E0 = rs_s[0], E1 = rs_s[64];
        int len = E1 - E0;
        int s  = E0 + (int)(((long long)len * grp) >> 5);
        int en = E0 + (int)(((long long)len * (grp + 1)) >> 5);

        if (s < en) {
            // binary search: largest nl with rs_s[nl] <= s
            int lo = 0, hi = 63;
            while (lo < hi) {
                int mid = (lo + hi + 1) >> 1;
                if (rs_s[mid] <= s) lo = mid; else hi = mid - 1;
            }
            int nl = lo;
            int nxt = rs_s[nl + 1];

            float acc[8];
#pragma unroll
            for (int c = 0; c < 8; c++) acc[c] = 0.f;

            auto flushf = [&]() {
#pragma unroll
                for (int cc = 0; cc < 8; cc++) {
                    int c = (cc + t) & 7;   // bank-rotate by lane
                    atomicAdd(&As[(t * 8 + c) * AST + nl], acc[c]);
                    acc[c] = 0.f;
                }
            };
            auto adv = [&](int ee) {
                if (ee >= nxt) {
                    flushf();
                    do { nl++; } while (rs_s[nl + 1] <= ee);
                    nxt = rs_s[nl + 1];
                }
            };
            auto accq = [&](uint4 q, float w) {
                float2 f;
                f = __half22float2(*(half2*)&q.x); acc[0] += w * f.x; acc[1] += w * f.y;
                f = __half22float2(*(half2*)&q.y); acc[2] += w * f.x; acc[3] += w * f.y;
                f = __half22float2(*(half2*)&q.z); acc[4] += w * f.x; acc[5] += w * f.y;
                f = __half22float2(*(half2*)&q.w); acc[6] += w * f.x; acc[7] += w * f.y;
            };
            auto accp = [&](float4 p0, float4 p1, float w) {
                acc[0] += w * p0.x; acc[1] += w * p0.y; acc[2] += w * p0.z; acc[3] += w * p0.w;
                acc[4] += w * p1.x; acc[5] += w * p1.y; acc[6] += w * p1.z; acc[7] += w * p1.w;
            };

            int ee = s;
            for (; ee + 3 < en; ee += 4) {
                int2 c0 = csr[ee];
                int2 c1 = csr[ee + 1];
                int2 c2 = csr[ee + 2];
                int2 c3 = csr[ee + 3];
                if (IN16) {
                    uint4 q0 = h16[(size_t)c0.x * 8 + t];
                    uint4 q1 = h16[(size_t)c1.x * 8 + t];
                    uint4 q2 = h16[(size_t)c2.x * 8 + t];
                    uint4 q3 = h16[(size_t)c3.x * 8 + t];
                    adv(ee);     accq(q0, __int_as_float(c0.y));
                    adv(ee + 1); accq(q1, __int_as_float(c1.y));
                    adv(ee + 2); accq(q2, __int_as_float(c2.y));
                    adv(ee + 3); accq(q3, __int_as_float(c3.y));
                } else {
                    float4 p00 = h32[(size_t)c0.x * 16 + 2 * t];
                    float4 p01 = h32[(size_t)c0.x * 16 + 2 * t + 1];
                    float4 p10 = h32[(size_t)c1.x * 16 + 2 * t];
                    float4 p11 = h32[(size_t)c1.x * 16 + 2 * t + 1];
                    float4 p20 = h32[(size_t)c2.x * 16 + 2 * t];
                    float4 p21 = h32[(size_t)c2.x * 16 + 2 * t + 1];
                    float4 p30 = h32[(size_t)c3.x * 16 + 2 * t];
                    float4 p31 = h32[(size_t)c3.x * 16 + 2 * t + 1];
                    adv(ee);     accp(p00, p01, __int_as_float(c0.y));
                    adv(ee + 1); accp(p10, p11, __int_as_float(c1.y));
                    adv(ee + 2); accp(p20, p21, __int_as_float(c2.y));
                    adv(ee + 3); accp(p30, p31, __int_as_float(c3.y));
                }
            }
            for (; ee < en; ee++) {
                int2 c0 = csr[ee];
                adv(ee);
                if (IN16) accq(h16[(size_t)c0.x * 8 + t], __int_as_float(c0.y));
                else      accp(h32[(size_t)c0.x * 16 + 2 * t],
                               h32[(size_t)c0.x * 16 + 2 * t + 1],
                               __int_as_float(c0.y));
            }
            flushf();
        }
    }
    __syncthreads();

    // ---- Phase 1.5: As[k][nl] = di * As[k][nl] + di^2 * self ----
    {
#pragma unroll
        for (int g = 0; g < 2; g++) {
            int nl = g * 32 + grp;
            int n = base + nl;
            float di = g_dinv[m][n];
            float d2 = di * di;
            float selfv[8];
            if (IN16) {
                uint4 q = h16[(size_t)n * 8 + t];
                float2 f0 = __half22float2(*(half2*)&q.x);
                float2 f1 = __half22float2(*(half2*)&q.y);
                float2 f2 = __half22float2(*(half2*)&q.z);
                float2 f3 = __half22float2(*(half2*)&q.w);
                selfv[0] = f0.x; selfv[1] = f0.y; selfv[2] = f1.x; selfv[3] = f1.y;
                selfv[4] = f2.x; selfv[5] = f2.y; selfv[6] = f3.x; selfv[7] = f3.y;
            } else {
                float4 p0 = h32[(size_t)n * 16 + 2 * t];
                float4 p1 = h32[(size_t)n * 16 + 2 * t + 1];
                selfv[0] = p0.x; selfv[1] = p0.y; selfv[2] = p0.z; selfv[3] = p0.w;
                selfv[4] = p1.x; selfv[5] = p1.y; selfv[6] = p1.z; selfv[7] = p1.w;
            }
#pragma unroll
            for (int c = 0; c < 8; c++) {
                float v = As[(t * 8 + c) * AST + nl];
                As[(t * 8 + c) * AST + nl] = di * v + d2 * selfv[c];
            }
        }
    }
    __syncthreads();

    // ---- Phase 2: D = As^T @ W + b (+ReLU), packed f32x2 FMAs ----
    {
        int tx = tid & 15;   // n group (4 cols)
        int ty = tid >> 4;   // m group (4 rows)

        unsigned long long acc[2][4];
#pragma unroll
        for (int p = 0; p < 2; p++)
#pragma unroll
            for (int n = 0; n < 4; n++) acc[p][n] = 0ull;

#pragma unroll
        for (int k = 0; k < 64; k++) {
            float4 wv = *(const float4*)&Ws[k * 64 + tx * 4];
            unsigned long long wp0 = d_bcast2(wv.x);
            unsigned long long wp1 = d_bcast2(wv.y);
            unsigned long long wp2 = d_bcast2(wv.z);
            unsigned long long wp3 = d_bcast2(wv.w);
            unsigned long long a0 = *(const unsigned long long*)&As[k * AST + ty * 4];
            unsigned long long a1 = *(const unsigned long long*)&As[k * AST + ty * 4 + 2];
            d_fma2(acc[0][0], a0, wp0); d_fma2(acc[1][0], a1, wp0);
            d_fma2(acc[0][1], a0, wp1); d_fma2(acc[1][1], a1, wp1);
            d_fma2(acc[0][2], a0, wp2); d_fma2(acc[1][2], a1, wp2);
            d_fma2(acc[0][3], a0, wp3); d_fma2(acc[1][3], a1, wp3);
        }

        float4 bb = ((const float4*)bj)[tx];
#pragma unroll
        for (int p = 0; p < 2; p++) {
            float2 u0 = d_unpack2(acc[p][0]);
            float2 u1 = d_unpack2(acc[p][1]);
            float2 u2 = d_unpack2(acc[p][2]);
            float2 u3 = d_unpack2(acc[p][3]);
            float4 r0 = make_float4(u0.x + bb.x, u1.x + bb.y, u2.x + bb.z, u3.x + bb.w);
            float4 r1 = make_float4(u0.y + bb.x, u1.y + bb.y, u2.y + bb.z, u3.y + bb.w);
            if (relu) {
                r0.x = fmaxf(r0.x, 0.f); r0.y = fmaxf(r0.y, 0.f);
                r0.z = fmaxf(r0.z, 0.f); r0.w = fmaxf(r0.w, 0.f);
                r1.x = fmaxf(r1.x, 0.f); r1.y = fmaxf(r1.y, 0.f);
                r1.z = fmaxf(r1.z, 0.f); r1.w = fmaxf(r1.w, 0.f);
            }
            size_t row0 = (size_t)tile * 64 + ty * 4 + 2 * p;
            if (OUT16) {
                half2 p00 = __floats2half2_rn(r0.x, r0.y);
                half2 p01 = __floats2half2_rn(r0.z, r0.w);
                half2 p10 = __floats2half2_rn(r1.x, r1.y);
                half2 p11 = __floats2half2_rn(r1.z, r1.w);
                uint2 o0, o1;
                o0.x = *(unsigned int*)&p00; o0.y = *(unsigned int*)&p01;
                o1.x = *(unsigned int*)&p10; o1.y = *(unsigned int*)&p11;
                ((uint2*)hout)[((size_t)m * NN + row0) * 16 + tx] = o0;
                ((uint2*)hout)[((size_t)m * NN + row0 + 1) * 16 + tx] = o1;
            } else {
                ((float4*)hout)[((size_t)m * NN + row0) * 16 + tx] = r0;
                ((float4*)hout)[((size_t)m * NN + row0 + 1) * 16 + tx] = r1;
            }
        }
    }
}

// ---------------- launcher ----------------
extern "C" void kernel_launch(void* const* d_in, const int* in_sizes, int n_in,
                              void* d_out, int out_size) {
    const float* x  = (const float*)d_in[0];
    const int*   ei = (const int*)d_in[1];   // int32 (JAX demotes int64)
    const float* W  = (const float*)d_in[2];
    const float* b  = (const float*)d_in[3];
    float*       out = (float*)d_out;

    void* hA;
    void* hB;
    cudaGetSymbolAddress(&hA, g_hA);
    cudaGetSymbolAddress(&hB, g_hB);

    // ---- CSR build for both members ----
    k_zero_deg<<<2 * NN / 256, 256>>>();
    k_count<<<2 * NE / 256, 256>>>(ei);
    k_blocksum<<<512, 256>>>();
    k_scanb<<<2, 256>>>();
    k_rowstart<<<512, 256>>>();
    k_fill<<<2 * NE / 256, 256>>>(ei);

    // ---- 12 fused layers, both members per launch ----
    void* bufs[2] = { hA, hB };
    k_layer<false, true><<<2048, 256>>>(x, bufs[0], W, b, 0, 1);
    const void* in = bufs[0];
    for (int j = 1; j <= 10; j++) {
        void* outp = bufs[j & 1];
        k_layer<true, true><<<2048, 256>>>(in, outp, W, b, j, 1);
        in = outp;
    }
    k_layer<true, false><<<2048, 256>>>(in, out, W, b, 11, 0);
}

// round 15
// speedup vs baseline: 1.8866x; 1.8866x over previous
#include <cuda_runtime.h>
#include <cuda_fp16.h>

#define NN 65536
#define NE 1048576
#define DD 64
#define NL 12
#define NM 2
#define AST 68   // As_T row stride (floats)
#define NTILE 2048
#define GRID_P 888   // 6 blocks/SM * 148 SMs: one full wave

// ---- device scratch (static allocation only) ----
__device__ __half g_hA[NM][NN * DD];     // fp16 ping
__device__ __half g_hB[NM][NN * DD];     // fp16 pong
__device__ float g_dinv[NM][NN];
__device__ int   g_deg[NM][NN];
__device__ int   g_rowstart[NM][NN + 1];
__device__ int   g_cursor[NM][NN];
__device__ int2  g_csr[NM][NE];          // {src, bitcast(dinv[src])}
__device__ int   g_bsum[NM * 256];
__device__ int   g_boff[NM * 256];
__device__ int   g_tilectr[NL];          // work-stealing counters, one per layer

// ---- f32x2 packed helpers ----
__device__ __forceinline__ unsigned long long d_bcast2(float x) {
    unsigned long long r;
    asm("mov.b64 %0, {%1, %1};" : "=l"(r) : "f"(x));
    return r;
}
__device__ __forceinline__ void d_fma2(unsigned long long& d,
                                       unsigned long long a,
                                       unsigned long long b) {
    asm("fma.rn.f32x2 %0, %1, %2, %3;" : "=l"(d) : "l"(a), "l"(b), "l"(d));
}
__device__ __forceinline__ float2 d_unpack2(unsigned long long v) {
    float2 f;
    asm("mov.b64 {%0, %1}, %2;" : "=f"(f.x), "=f"(f.y) : "l"(v));
    return f;
}

// ---------------- CSR build ----------------
__global__ void k_zero_deg() {
    int i = blockIdx.x * blockDim.x + threadIdx.x;
    ((int*)g_deg)[i] = 0;
    if (i < NL) g_tilectr[i] = 0;
}

__global__ void k_count(const int* __restrict__ ei) {
    int gi = blockIdx.x * blockDim.x + threadIdx.x;
    int m = gi >> 20;
    int e = gi & (NE - 1);
    int d = ei[(size_t)m * 2 * NE + NE + e] & (NN - 1);
    atomicAdd(&g_deg[m][d], 1);
}

__global__ void k_blocksum() {
    __shared__ int red[256];
    int m = blockIdx.x >> 8;
    int cb = blockIdx.x & 255;
    int node = cb * 256 + threadIdx.x;
    int d = g_deg[m][node];
    g_dinv[m][node] = rsqrtf((float)d + 1.0f);
    red[threadIdx.x] = d;
    __syncthreads();
    for (int off = 128; off > 0; off >>= 1) {
        if (threadIdx.x < off) red[threadIdx.x] += red[threadIdx.x + off];
        __syncthreads();
    }
    if (threadIdx.x == 0) g_bsum[m * 256 + cb] = red[0];
}

__global__ void k_scanb() {
    __shared__ int s[256];
    int t = threadIdx.x;
    int v = g_bsum[blockIdx.x * 256 + t];
    s[t] = v;
    __syncthreads();
    for (int off = 1; off < 256; off <<= 1) {
        int u = (t >= off) ? s[t - off] : 0;
        __syncthreads();
        s[t] += u;
        __syncthreads();
    }
    g_boff[blockIdx.x * 256 + t] = s[t] - v;
}

__global__ void k_rowstart() {
    __shared__ int s[256];
    int m = blockIdx.x >> 8;
    int cb = blockIdx.x & 255;
    int t = threadIdx.x;
    int node = cb * 256 + t;
    int d = g_deg[m][node];
    s[t] = d;
    __syncthreads();
    for (int off = 1; off < 256; off <<= 1) {
        int u = (t >= off) ? s[t - off] : 0;
        __syncthreads();
        s[t] += u;
        __syncthreads();
    }
    int rs = g_boff[m * 256 + cb] + s[t] - d;
    g_rowstart[m][node] = rs;
    g_cursor[m][node] = rs;
    if (node == NN - 1) g_rowstart[m][NN] = rs + d;
}

__global__ void k_fill(const int* __restrict__ ei) {
    int gi = blockIdx.x * blockDim.x + threadIdx.x;
    int m = gi >> 20;
    int e = gi & (NE - 1);
    int s = ei[(size_t)m * 2 * NE + e] & (NN - 1);
    int d = ei[(size_t)m * 2 * NE + NE + e] & (NN - 1);
    int pos = atomicAdd(&g_cursor[m][d], 1);
    g_csr[m][pos] = make_int2(s, __float_as_int(g_dinv[m][s]));
}

// ---------------- fused layer (persistent, work-stealing) ----------------
// One wave of 888 blocks; each steals tiles via g_tilectr[j].
// Per tile: Phase 1 gather (4-edge chunks) -> As_T; Phase 2 f32x2 GEMM.
template<bool IN16, bool OUT16>
__global__ __launch_bounds__(256, 6) void k_layer(
    const void* __restrict__ hin,
    void* __restrict__ hout,
    const float* __restrict__ Wbase,
    const float* __restrict__ bbase,
    int j, int relu)
{
    __shared__ float As[64 * AST];   // TRANSPOSED: As[k][m]
    __shared__ float Ws[64 * 64];
    __shared__ int s_tile;

    int tid = threadIdx.x;

    while (true) {
        if (tid == 0) s_tile = atomicAdd(&g_tilectr[j], 1);
        __syncthreads();            // publishes s_tile; also guards smem reuse
        int gidx = s_tile;
        if (gidx >= NTILE) return;

        int m = gidx >> 10;
        int tile = gidx & 1023;

        const float* Wj = Wbase + ((size_t)m * NL + j) * DD * DD;
        const float* bj = bbase + ((size_t)m * NL + j) * DD;

        // load W tile
        {
            const float4* W4 = (const float4*)Wj;
            float4* Ws4 = (float4*)Ws;
#pragma unroll
            for (int k = 0; k < 4; k++) Ws4[tid + k * 256] = W4[tid + k * 256];
        }

        // ---- Phase 1: aggregate 64 rows of h into As_T ----
        {
            int t = tid & 7;         // 16-byte lane (8 features)
            int grp = tid >> 3;      // 32 node groups
            const int2* csr = g_csr[m];

            const uint4*  h16 = (const uint4*)hin + (IN16 ? (size_t)m * NN * 8 : 0);
            const float4* h32 = (const float4*)hin + (IN16 ? 0 : (size_t)m * NN * 16);

#pragma unroll
            for (int g = 0; g < 2; g++) {
                int nl = g * 32 + grp;
                int n = tile * 64 + nl;
                int beg = g_rowstart[m][n];
                int end = g_rowstart[m][n + 1];

                float acc[8];
#pragma unroll
                for (int c = 0; c < 8; c++) acc[c] = 0.f;

                auto accq = [&](uint4 q, float w) {
                    float2 f;
                    f = __half22float2(*(half2*)&q.x); acc[0] += w * f.x; acc[1] += w * f.y;
                    f = __half22float2(*(half2*)&q.y); acc[2] += w * f.x; acc[3] += w * f.y;
                    f = __half22float2(*(half2*)&q.z); acc[4] += w * f.x; acc[5] += w * f.y;
                    f = __half22float2(*(half2*)&q.w); acc[6] += w * f.x; acc[7] += w * f.y;
                };
                auto accp = [&](float4 p0, float4 p1, float w) {
                    acc[0] += w * p0.x; acc[1] += w * p0.y; acc[2] += w * p0.z; acc[3] += w * p0.w;
                    acc[4] += w * p1.x; acc[5] += w * p1.y; acc[6] += w * p1.z; acc[7] += w * p1.w;
                };
                auto one = [&](int ee) {
                    int2 sw = csr[ee];
                    float w = __int_as_float(sw.y);
                    if (IN16) accq(h16[(size_t)sw.x * 8 + t], w);
                    else      accp(h32[(size_t)sw.x * 16 + 2 * t],
                                   h32[(size_t)sw.x * 16 + 2 * t + 1], w);
                };

                int e = beg;
                if ((e & 1) && e < end) { one(e); e++; }   // align for int4 CSR loads

                for (; e + 3 < end; e += 4) {
                    int4 cA = *(const int4*)&csr[e];        // {s0,w0,s1,w1}
                    int4 cB = *(const int4*)&csr[e + 2];    // {s2,w2,s3,w3}
                    if (IN16) {
                        uint4 q0 = h16[(size_t)cA.x * 8 + t];
                        uint4 q1 = h16[(size_t)cA.z * 8 + t];
                        uint4 q2 = h16[(size_t)cB.x * 8 + t];
                        uint4 q3 = h16[(size_t)cB.z * 8 + t];
                        accq(q0, __int_as_float(cA.y));
                        accq(q1, __int_as_float(cA.w));
                        accq(q2, __int_as_float(cB.y));
                        accq(q3, __int_as_float(cB.w));
                    } else {
                        float4 p00 = h32[(size_t)cA.x * 16 + 2 * t];
                        float4 p01 = h32[(size_t)cA.x * 16 + 2 * t + 1];
                        float4 p10 = h32[(size_t)cA.z * 16 + 2 * t];
                        float4 p11 = h32[(size_t)cA.z * 16 + 2 * t + 1];
                        accp(p00, p01, __int_as_float(cA.y));
                        accp(p10, p11, __int_as_float(cA.w));
                        float4 p20 = h32[(size_t)cB.x * 16 + 2 * t];
                        float4 p21 = h32[(size_t)cB.x * 16 + 2 * t + 1];
                        float4 p30 = h32[(size_t)cB.z * 16 + 2 * t];
                        float4 p31 = h32[(size_t)cB.z * 16 + 2 * t + 1];
                        accp(p20, p21, __int_as_float(cB.y));
                        accp(p30, p31, __int_as_float(cB.w));
                    }
                }
                for (; e < end; e++) one(e);

                float di = g_dinv[m][n];
                float d2 = di * di;
                float selfv[8];
                if (IN16) {
                    uint4 q = h16[(size_t)n * 8 + t];
                    float2 f0 = __half22float2(*(half2*)&q.x);
                    float2 f1 = __half22float2(*(half2*)&q.y);
                    float2 f2 = __half22float2(*(half2*)&q.z);
                    float2 f3 = __half22float2(*(half2*)&q.w);
                    selfv[0] = f0.x; selfv[1] = f0.y; selfv[2] = f1.x; selfv[3] = f1.y;
                    selfv[4] = f2.x; selfv[5] = f2.y; selfv[6] = f3.x; selfv[7] = f3.y;
                } else {
                    float4 p0 = h32[(size_t)n * 16 + 2 * t];
                    float4 p1 = h32[(size_t)n * 16 + 2 * t + 1];
                    selfv[0] = p0.x; selfv[1] = p0.y; selfv[2] = p0.z; selfv[3] = p0.w;
                    selfv[4] = p1.x; selfv[5] = p1.y; selfv[6] = p1.z; selfv[7] = p1.w;
                }
                int k0 = t * 8;
#pragma unroll
                for (int c = 0; c < 8; c++)
                    As[(k0 + c) * AST + nl] = di * acc[c] + d2 * selfv[c];
            }
        }
        __syncthreads();

        // ---- Phase 2: D = As^T @ W + b (+ReLU), packed f32x2 FMAs ----
        {
            int tx = tid & 15;   // n group (4 cols)
            int ty = tid >> 4;   // m group (4 rows)

            unsigned long long acc[2][4];
#pragma unroll
            for (int p = 0; p < 2; p++)
#pragma unroll
                for (int n = 0; n < 4; n++) acc[p][n] = 0ull;

#pragma unroll
            for (int k = 0; k < 64; k++) {
                float4 wv = *(const float4*)&Ws[k * 64 + tx * 4];
                unsigned long long wp0 = d_bcast2(wv.x);
                unsigned long long wp1 = d_bcast2(wv.y);
                unsigned long long wp2 = d_bcast2(wv.z);
                unsigned long long wp3 = d_bcast2(wv.w);
                unsigned long long a0 = *(const unsigned long long*)&As[k * AST + ty * 4];
                unsigned long long a1 = *(const unsigned long long*)&As[k * AST + ty * 4 + 2];
                d_fma2(acc[0][0], a0, wp0); d_fma2(acc[1][0], a1, wp0);
                d_fma2(acc[0][1], a0, wp1); d_fma2(acc[1][1], a1, wp1);
                d_fma2(acc[0][2], a0, wp2); d_fma2(acc[1][2], a1, wp2);
                d_fma2(acc[0][3], a0, wp3); d_fma2(acc[1][3], a1, wp3);
            }

            float4 bb = ((const float4*)bj)[tx];
#pragma unroll
            for (int p = 0; p < 2; p++) {
                float2 u0 = d_unpack2(acc[p][0]);
                float2 u1 = d_unpack2(acc[p][1]);
                float2 u2 = d_unpack2(acc[p][2]);
                float2 u3 = d_unpack2(acc[p][3]);
                float4 r0 = make_float4(u0.x + bb.x, u1.x + bb.y, u2.x + bb.z, u3.x + bb.w);
                float4 r1 = make_float4(u0.y + bb.x, u1.y + bb.y, u2.y + bb.z, u3.y + bb.w);
                if (relu) {
                    r0.x = fmaxf(r0.x, 0.f); r0.y = fmaxf(r0.y, 0.f);
                    r0.z = fmaxf(r0.z, 0.f); r0.w = fmaxf(r0.w, 0.f);
                    r1.x = fmaxf(r1.x, 0.f); r1.y = fmaxf(r1.y, 0.f);
                    r1.z = fmaxf(r1.z, 0.f); r1.w = fmaxf(r1.w, 0.f);
                }
                size_t row0 = (size_t)tile * 64 + ty * 4 + 2 * p;
                if (OUT16) {
                    half2 p00 = __floats2half2_rn(r0.x, r0.y);
                    half2 p01 = __floats2half2_rn(r0.z, r0.w);
                    half2 p10 = __floats2half2_rn(r1.x, r1.y);
                    half2 p11 = __floats2half2_rn(r1.z, r1.w);
                    uint2 o0, o1;
                    o0.x = *(unsigned int*)&p00; o0.y = *(unsigned int*)&p01;
                    o1.x = *(unsigned int*)&p10; o1.y = *(unsigned int*)&p11;
                    ((uint2*)hout)[((size_t)m * NN + row0) * 16 + tx] = o0;
                    ((uint2*)hout)[((size_t)m * NN + row0 + 1) * 16 + tx] = o1;
                } else {
                    ((float4*)hout)[((size_t)m * NN + row0) * 16 + tx] = r0;
                    ((float4*)hout)[((size_t)m * NN + row0 + 1) * 16 + tx] = r1;
                }
            }
        }
        // loop: barrier at top of next iteration guards As/Ws reuse
    }
}

// ---------------- launcher ----------------
extern "C" void kernel_launch(void* const* d_in, const int* in_sizes, int n_in,
                              void* d_out, int out_size) {
    const float* x  = (const float*)d_in[0];
    const int*   ei = (const int*)d_in[1];   // int32 (JAX demotes int64)
    const float* W  = (const float*)d_in[2];
    const float* b  = (const float*)d_in[3];
    float*       out = (float*)d_out;

    void* hA;
    void* hB;
    cudaGetSymbolAddress(&hA, g_hA);
    cudaGetSymbolAddress(&hB, g_hB);

    // ---- CSR build for both members (also zeroes tile counters) ----
    k_zero_deg<<<2 * NN / 256, 256>>>();
    k_count<<<2 * NE / 256, 256>>>(ei);
    k_blocksum<<<512, 256>>>();
    k_scanb<<<2, 256>>>();
    k_rowstart<<<512, 256>>>();
    k_fill<<<2 * NE / 256, 256>>>(ei);

    // ---- 12 fused layers, persistent single-wave with stealing ----
    void* bufs[2] = { hA, hB };
    k_layer<false, true><<<GRID_P, 256>>>(x, bufs[0], W, b, 0, 1);
    const void* in = bufs[0];
    for (int j = 1; j <= 10; j++) {
        void* outp = bufs[j & 1];
        k_layer<true, true><<<GRID_P, 256>>>(in, outp, W, b, j, 1);
        in = outp;
    }
    k_layer<true, false><<<GRID_P, 256>>>(in, out, W, b, 11, 0);
}

// round 17
// speedup vs baseline: 2.0119x; 1.0664x over previous
#include <cuda_runtime.h>
#include <cuda_fp16.h>

#define NN 65536
#define NE 1048576
#define DD 64
#define NL 12
#define NM 2
#define AST 68   // As_T row stride (floats)

// ---- device scratch (static allocation only) ----
__device__ __half g_hA[NM][NN * DD];     // fp16 ping (pre-scaled: dinv[n]*h[n])
__device__ __half g_hB[NM][NN * DD];     // fp16 pong
__device__ float g_dinv[NM][NN];
__device__ int   g_deg[NM][NN];
__device__ int   g_rowstart[NM][NN + 1];
__device__ int   g_cursor[NM][NN];
__device__ unsigned short g_csr16[NM][NE];   // bare src index per edge
__device__ int   g_bsum[NM * 256];
__device__ int   g_boff[NM * 256];

// ---- f32x2 packed helpers ----
__device__ __forceinline__ unsigned long long d_bcast2(float x) {
    unsigned long long r;
    asm("mov.b64 %0, {%1, %1};" : "=l"(r) : "f"(x));
    return r;
}
__device__ __forceinline__ void d_fma2(unsigned long long& d,
                                       unsigned long long a,
                                       unsigned long long b) {
    asm("fma.rn.f32x2 %0, %1, %2, %3;" : "=l"(d) : "l"(a), "l"(b), "l"(d));
}
__device__ __forceinline__ float2 d_unpack2(unsigned long long v) {
    float2 f;
    asm("mov.b64 {%0, %1}, %2;" : "=f"(f.x), "=f"(f.y) : "l"(v));
    return f;
}

// ---------------- CSR build (5 launches; first k_layer is launch #5 for ncu) ----------------
__global__ void k_count(const int* __restrict__ ei) {
    int gi = blockIdx.x * blockDim.x + threadIdx.x;
    int m = gi >> 20;
    int e = gi & (NE - 1);
    int d = ei[(size_t)m * 2 * NE + NE + e] & (NN - 1);
    atomicAdd(&g_deg[m][d], 1);
}

__global__ void k_blocksum() {
    __shared__ int red[256];
    int m = blockIdx.x >> 8;
    int cb = blockIdx.x & 255;
    int node = cb * 256 + threadIdx.x;
    int d = g_deg[m][node];
    g_dinv[m][node] = rsqrtf((float)d + 1.0f);
    red[threadIdx.x] = d;
    __syncthreads();
    for (int off = 128; off > 0; off >>= 1) {
        if (threadIdx.x < off) red[threadIdx.x] += red[threadIdx.x + off];
        __syncthreads();
    }
    if (threadIdx.x == 0) g_bsum[m * 256 + cb] = red[0];
}

__global__ void k_scanb() {
    __shared__ int s[256];
    int t = threadIdx.x;
    int v = g_bsum[blockIdx.x * 256 + t];
    s[t] = v;
    __syncthreads();
    for (int off = 1; off < 256; off <<= 1) {
        int u = (t >= off) ? s[t - off] : 0;
        __syncthreads();
        s[t] += u;
        __syncthreads();
    }
    g_boff[blockIdx.x * 256 + t] = s[t] - v;
}

// rowstart/cursor + prescale x -> g_hA (fp16, dinv-scaled) + zero deg for next replay
__global__ void k_rowstart_prescale(const float* __restrict__ x) {
    __shared__ int s[256];
    int m = blockIdx.x >> 8;
    int cb = blockIdx.x & 255;
    int t = threadIdx.x;
    int node = cb * 256 + t;
    int d = g_deg[m][node];
    s[t] = d;
    __syncthreads();
    for (int off = 1; off < 256; off <<= 1) {
        int u = (t >= off) ? s[t - off] : 0;
        __syncthreads();
        s[t] += u;
        __syncthreads();
    }
    int rs = g_boff[m * 256 + cb] + s[t] - d;
    g_rowstart[m][node] = rs;
    g_cursor[m][node] = rs;
    if (node == NN - 1) g_rowstart[m][NN] = rs + d;

    float di = rsqrtf((float)d + 1.0f);   // bit-identical to g_dinv
    const float4* xr = (const float4*)(x + ((size_t)m * NN + node) * DD);
    uint4* hw = (uint4*)(g_hA[m] + (size_t)node * DD);
#pragma unroll
    for (int i = 0; i < 8; i++) {        // 8 uint4 = 64 halves = full row (was 4: BUG)
        float4 a = xr[2 * i];
        float4 b = xr[2 * i + 1];
        half2 h0 = __floats2half2_rn(di * a.x, di * a.y);
        half2 h1 = __floats2half2_rn(di * a.z, di * a.w);
        half2 h2 = __floats2half2_rn(di * b.x, di * b.y);
        half2 h3 = __floats2half2_rn(di * b.z, di * b.w);
        uint4 o;
        o.x = *(unsigned int*)&h0; o.y = *(unsigned int*)&h1;
        o.z = *(unsigned int*)&h2; o.w = *(unsigned int*)&h3;
        hw[i] = o;
    }

    g_deg[m][node] = 0;
}

__global__ void k_fill(const int* __restrict__ ei) {
    int gi = blockIdx.x * blockDim.x + threadIdx.x;
    int m = gi >> 20;
    int e = gi & (NE - 1);
    int s = ei[(size_t)m * 2 * NE + e] & (NN - 1);
    int d = ei[(size_t)m * 2 * NE + NE + e] & (NN - 1);
    int pos = atomicAdd(&g_cursor[m][d], 1);
    g_csr16[m][pos] = (unsigned short)s;
}

// ---------------- fused layer ----------------
// hin/hout are BASE pointers of [NM][NN*DD] fp16 buffers (member offset inside).
// agg[n] = dinv[n]*(sum_e hs[src] + hs[n]); Phase 2: GEMM + bias.
// OUT16: store fp16(dinv * relu(.)); else raw fp32 to d_out.
template<bool OUT16>
__global__ __launch_bounds__(256, 6) void k_layer(
    const __half* __restrict__ hin,
    void* __restrict__ hout,
    const float* __restrict__ Wbase,
    const float* __restrict__ bbase,
    int j)
{
    __shared__ float As[64 * AST];   // TRANSPOSED: As[k][nl]
    __shared__ float Ws[64 * 64];

    int tid = threadIdx.x;
    int m = blockIdx.x >> 10;
    int tile = blockIdx.x & 1023;
    int base = tile * 64;

    const float* Wj = Wbase + ((size_t)m * NL + j) * DD * DD;
    const float* bj = bbase + ((size_t)m * NL + j) * DD;

    {
        const float4* W4 = (const float4*)Wj;
        float4* Ws4 = (float4*)Ws;
#pragma unroll
        for (int k = 0; k < 4; k++) Ws4[tid + k * 256] = W4[tid + k * 256];
    }

    // ---- Phase 1: aggregate 64 rows of hs into As_T ----
    {
        int t = tid & 7;
        int grp = tid >> 3;
        const unsigned short* csr = g_csr16[m];
        const uint4* h16 = (const uint4*)(hin + (size_t)m * NN * DD);

#pragma unroll
        for (int g = 0; g < 2; g++) {
            int nl = g * 32 + grp;
            int n = base + nl;
            int beg = g_rowstart[m][n];
            int end = g_rowstart[m][n + 1];

            float acc[8];
#pragma unroll
            for (int c = 0; c < 8; c++) acc[c] = 0.f;

            auto accq = [&](uint4 q) {
                float2 f;
                f = __half22float2(*(half2*)&q.x); acc[0] += f.x; acc[1] += f.y;
                f = __half22float2(*(half2*)&q.y); acc[2] += f.x; acc[3] += f.y;
                f = __half22float2(*(half2*)&q.z); acc[4] += f.x; acc[5] += f.y;
                f = __half22float2(*(half2*)&q.w); acc[6] += f.x; acc[7] += f.y;
            };

            int e = beg;
            for (; (e & 3) && e < end; e++)
                accq(h16[(size_t)csr[e] * 8 + t]);

            for (; e + 3 < end; e += 4) {
                uint2 c4 = *(const uint2*)&csr[e];
                int s0 = c4.x & 0xFFFF;
                int s1 = c4.x >> 16;
                int s2 = c4.y & 0xFFFF;
                int s3 = c4.y >> 16;
                uint4 q0 = h16[(size_t)s0 * 8 + t];
                uint4 q1 = h16[(size_t)s1 * 8 + t];
                uint4 q2 = h16[(size_t)s2 * 8 + t];
                uint4 q3 = h16[(size_t)s3 * 8 + t];
                accq(q0); accq(q1); accq(q2); accq(q3);
            }
            for (; e < end; e++)
                accq(h16[(size_t)csr[e] * 8 + t]);

            accq(h16[(size_t)n * 8 + t]);   // self term
            float di = g_dinv[m][n];
            int k0 = t * 8;
#pragma unroll
            for (int c = 0; c < 8; c++)
                As[(k0 + c) * AST + nl] = di * acc[c];
        }
    }
    __syncthreads();

    // ---- Phase 2: D = As^T @ W + b, packed f32x2 FMAs ----
    {
        int tx = tid & 15;
        int ty = tid >> 4;

        unsigned long long acc[2][4];
#pragma unroll
        for (int p = 0; p < 2; p++)
#pragma unroll
            for (int n = 0; n < 4; n++) acc[p][n] = 0ull;

#pragma unroll
        for (int k = 0; k < 64; k++) {
            float4 wv = *(const float4*)&Ws[k * 64 + tx * 4];
            unsigned long long wp0 = d_bcast2(wv.x);
            unsigned long long wp1 = d_bcast2(wv.y);
            unsigned long long wp2 = d_bcast2(wv.z);
            unsigned long long wp3 = d_bcast2(wv.w);
            unsigned long long a0 = *(const unsigned long long*)&As[k * AST + ty * 4];
            unsigned long long a1 = *(const unsigned long long*)&As[k * AST + ty * 4 + 2];
            d_fma2(acc[0][0], a0, wp0); d_fma2(acc[1][0], a1, wp0);
            d_fma2(acc[0][1], a0, wp1); d_fma2(acc[1][1], a1, wp1);
            d_fma2(acc[0][2], a0, wp2); d_fma2(acc[1][2], a1, wp2);
            d_fma2(acc[0][3], a0, wp3); d_fma2(acc[1][3], a1, wp3);
        }

        float4 bb = ((const float4*)bj)[tx];
#pragma unroll
        for (int p = 0; p < 2; p++) {
            float2 u0 = d_unpack2(acc[p][0]);
            float2 u1 = d_unpack2(acc[p][1]);
            float2 u2 = d_unpack2(acc[p][2]);
            float2 u3 = d_unpack2(acc[p][3]);
            float4 r0 = make_float4(u0.x + bb.x, u1.x + bb.y, u2.x + bb.z, u3.x + bb.w);
            float4 r1 = make_float4(u0.y + bb.x, u1.y + bb.y, u2.y + bb.z, u3.y + bb.w);
            size_t row0 = (size_t)base + ty * 4 + 2 * p;
            if (OUT16) {
                float di0 = g_dinv[m][row0];
                float di1 = g_dinv[m][row0 + 1];
                r0.x = di0 * fmaxf(r0.x, 0.f); r0.y = di0 * fmaxf(r0.y, 0.f);
                r0.z = di0 * fmaxf(r0.z, 0.f); r0.w = di0 * fmaxf(r0.w, 0.f);
                r1.x = di1 * fmaxf(r1.x, 0.f); r1.y = di1 * fmaxf(r1.y, 0.f);
                r1.z = di1 * fmaxf(r1.z, 0.f); r1.w = di1 * fmaxf(r1.w, 0.f);
                half2 p00 = __floats2half2_rn(r0.x, r0.y);
                half2 p01 = __floats2half2_rn(r0.z, r0.w);
                half2 p10 = __floats2half2_rn(r1.x, r1.y);
                half2 p11 = __floats2half2_rn(r1.z, r1.w);
                uint2 o0, o1;
                o0.x = *(unsigned int*)&p00; o0.y = *(unsigned int*)&p01;
                o1.x = *(unsigned int*)&p10; o1.y = *(unsigned int*)&p11;
                uint2* ho = (uint2*)((__half*)hout + (size_t)m * NN * DD);
                ho[row0 * 16 + tx] = o0;
                ho[(row0 + 1) * 16 + tx] = o1;
            } else {
                ((float4*)hout)[((size_t)m * NN + row0) * 16 + tx] = r0;
                ((float4*)hout)[((size_t)m * NN + row0 + 1) * 16 + tx] = r1;
            }
        }
    }
}

// ---------------- launcher ----------------
extern "C" void kernel_launch(void* const* d_in, const int* in_sizes, int n_in,
                              void* d_out, int out_size) {
    const float* x  = (const float*)d_in[0];
    const int*   ei = (const int*)d_in[1];   // int32 (JAX demotes int64)
    const float* W  = (const float*)d_in[2];
    const float* b  = (const float*)d_in[3];
    float*       out = (float*)d_out;

    __half* hA;
    __half* hB;
    cudaGetSymbolAddress((void**)&hA, g_hA);
    cudaGetSymbolAddress((void**)&hB, g_hB);

    // ---- CSR build: exactly 5 launches so k_layer j=0 is launch #5 (ncu -s 5) ----
    k_count<<<2 * NE / 256, 256>>>(ei);
    k_blocksum<<<512, 256>>>();
    k_scanb<<<2, 256>>>();
    k_rowstart_prescale<<<512, 256>>>(x);
    k_fill<<<2 * NE / 256, 256>>>(ei);

    // ---- 12 fused layers; activations pre-scaled fp16, ping-pong hA/hB ----
    __half* bufs[2] = { hA, hB };
    for (int j = 0; j <= 10; j++)
        k_layer<true><<<2048, 256>>>(bufs[j & 1], bufs[(j + 1) & 1], W, b, j);
    k_layer<false><<<2048, 256>>>(bufs[11 & 1], out, W, b, 11);
}